// round 1
// baseline (speedup 1.0000x reference)
#include <cuda_runtime.h>
#include <cstdint>

#define B_  64
#define S_  512
#define E_  512
#define H_  1024
#define M0_ 32768                 // B_*S_
#define OUT_ELEMS (M0_ * H_)      // 33554432
#define GRID_R 128
#define RECUR_SMEM ((128*64 + 64*132) * 4)   // Ws + hs = 66560 bytes

// ---------------- scratch (device globals; no allocation allowed) ----------
__device__ float    g_Z0[OUT_ELEMS];          // 128 MiB scratch: Z0, then h0
__device__ float    g_h[B_ * H_];             // current hidden state
__device__ float    g_part[8 * B_ * H_];      // k-split partial sums
__device__ unsigned g_arrive;                 // monotonic barrier counter
__device__ int      g_is64;                   // src dtype flag

// ---------------- src dtype detection --------------------------------------
// If src is int64 (little-endian, values in [0,32000)), every odd int32 slot
// of the first 16384 int64s is zero. If int32, 4096 consecutive zeros among
// real vocab draws is impossible in practice. Reads stay within 8192 int32s,
// which is in-bounds for both interpretations (element count is 32768).
__global__ void detect_src_kernel(const int* __restrict__ src) {
    __shared__ int red[256];
    int acc = 0;
    for (int i = threadIdx.x; i < 4096; i += 256) acc |= src[2 * i + 1];
    red[threadIdx.x] = acc;
    __syncthreads();
    for (int s = 128; s > 0; s >>= 1) {
        if (threadIdx.x < s) red[threadIdx.x] |= red[threadIdx.x + s];
        __syncthreads();
    }
    if (threadIdx.x == 0) g_is64 = (red[0] == 0) ? 1 : 0;
}

// ---------------- software grid barrier (persistent kernel) ----------------
// Monotonic ticket counter: needs no reset between launches or graph replays.
__device__ __forceinline__ void grid_barrier() {
    __syncthreads();
    if (threadIdx.x == 0) {
        __threadfence();
        unsigned ticket = atomicAdd(&g_arrive, 1u);
        unsigned target = ticket - (ticket % (unsigned)GRID_R) + (unsigned)GRID_R;
        while ((int)(*(volatile unsigned*)&g_arrive - target) < 0) {
            __nanosleep(32);
        }
        __threadfence();
    }
    __syncthreads();
}

// ---------------- big GEMM: C[M,1024] = A[M,K] @ W[K,1024] + b1 + b2 -------
// gather=1: A row m is emb[src[m]] (K = E_ = 512). gather=0: plain rows.
// Tiles: CTA 128x64, BK=16, thread 8x4, 256 threads. FMA-bound by design.
__global__ __launch_bounds__(256) void gemm_bias_kernel(
    const float* __restrict__ A, const float* __restrict__ emb,
    const int* __restrict__ src,
    const float* __restrict__ Wm,
    const float* __restrict__ b1, const float* __restrict__ b2,
    float* __restrict__ C, int K, int gather)
{
    __shared__ float As[16 * 132];   // [k][m], padded pitch
    __shared__ float Bs[16 * 64];    // [k][n]
    __shared__ int   sidx[128];

    const int tid = threadIdx.x;
    const int bx = blockIdx.x, ny = blockIdx.y;

    if (gather && tid < 128) {
        int rg = bx * 128 + tid;
        sidx[tid] = g_is64 ? src[2 * rg] : src[rg];
    }
    __syncthreads();

    const int mt = tid >> 4, nt = tid & 15;
    const int m0 = mt * 8, n0t = nt * 4;

    float acc[8][4];
    #pragma unroll
    for (int i = 0; i < 8; ++i)
        #pragma unroll
        for (int j = 0; j < 4; ++j) acc[i][j] = 0.0f;

    const int nktiles = K >> 4;
    for (int kt = 0; kt < nktiles; ++kt) {
        // A tile: 128 rows x 16 k, stored transposed As[k][m]
        #pragma unroll
        for (int it = 0; it < 2; ++it) {
            int task = tid + it * 256;
            int ml = task >> 2, q = task & 3;
            const float* ar = gather ? (emb + (size_t)sidx[ml] * E_)
                                     : (A + (size_t)(bx * 128 + ml) * K);
            float4 av = *(const float4*)(ar + (kt << 4) + (q << 2));
            As[(q * 4 + 0) * 132 + ml] = av.x;
            As[(q * 4 + 1) * 132 + ml] = av.y;
            As[(q * 4 + 2) * 132 + ml] = av.z;
            As[(q * 4 + 3) * 132 + ml] = av.w;
        }
        // B tile: 16 k x 64 n
        {
            int kk = tid >> 4, q = tid & 15;
            *(float4*)&Bs[kk * 64 + (q << 2)] =
                *(const float4*)&Wm[(size_t)((kt << 4) + kk) * H_ + ny * 64 + (q << 2)];
        }
        __syncthreads();

        #pragma unroll
        for (int kk = 0; kk < 16; ++kk) {
            float4 b4 = *(const float4*)&Bs[kk * 64 + n0t];
            float4 a0 = *(const float4*)&As[kk * 132 + m0];
            float4 a1 = *(const float4*)&As[kk * 132 + m0 + 4];
            float a[8] = {a0.x, a0.y, a0.z, a0.w, a1.x, a1.y, a1.z, a1.w};
            #pragma unroll
            for (int i = 0; i < 8; ++i) {
                acc[i][0] += a[i] * b4.x;
                acc[i][1] += a[i] * b4.y;
                acc[i][2] += a[i] * b4.z;
                acc[i][3] += a[i] * b4.w;
            }
        }
        __syncthreads();
    }

    const int gn = ny * 64 + n0t;
    float bx0 = b1[gn + 0] + b2[gn + 0];
    float bx1 = b1[gn + 1] + b2[gn + 1];
    float bx2 = b1[gn + 2] + b2[gn + 2];
    float bx3 = b1[gn + 3] + b2[gn + 3];
    #pragma unroll
    for (int i = 0; i < 8; ++i) {
        int row = bx * 128 + m0 + i;
        float4 r = make_float4(acc[i][0] + bx0, acc[i][1] + bx1,
                               acc[i][2] + bx2, acc[i][3] + bx3);
        *(float4*)&C[(size_t)row * H_ + gn] = r;
    }
}

// ---------------- persistent recurrence kernel ------------------------------
// h_t = tanh(Z[t] + h_{t-1} @ W), 512 steps, in-place: Z[t] <- h_t.
// 128 CTAs = 16 N-blocks (64 cols) x 8 K-splits (128 rows of W).
// W slice (32 KB) stays in smem for all steps. Two grid barriers per step.
__global__ __launch_bounds__(256) void rnn_recur_kernel(
    const float* __restrict__ W, float* __restrict__ Z,
    float* __restrict__ hid_out)
{
    extern __shared__ float dyn[];
    float* Ws = dyn;             // [128][64]  W[k0+kk][n0+nn]
    float* hs = dyn + 128 * 64;  // [64][132]  h[m][k0+kk] (padded pitch)

    const int tid = threadIdx.x;
    const int nb = blockIdx.x & 15, ks = blockIdx.x >> 4;
    const int n0 = nb * 64, k0 = ks * 128;

    // Load this CTA's W slice once; it persists across all 512 steps.
    for (int i = tid; i < 2048; i += 256) {
        int kk = i >> 4, q = i & 15;
        *(float4*)&Ws[kk * 64 + (q << 2)] =
            *(const float4*)&W[(size_t)(k0 + kk) * H_ + n0 + (q << 2)];
    }
    __syncthreads();

    const int mt = tid >> 4, nt = tid & 15;
    const int m0 = mt * 4, n0t = nt * 4;
    float* pp = &g_part[ks * (B_ * H_)];

    for (int t = 0; t < S_; ++t) {
        if (t > 0) {
            // stage h_{t-1}[0:64][k0:k0+128] into smem
            for (int i = tid; i < 2048; i += 256) {
                int m = i >> 5, q = i & 31;
                *(float4*)&hs[m * 132 + (q << 2)] =
                    *(const float4*)&g_h[m * H_ + k0 + (q << 2)];
            }
            __syncthreads();

            float acc[4][4];
            #pragma unroll
            for (int i = 0; i < 4; ++i)
                #pragma unroll
                for (int j = 0; j < 4; ++j) acc[i][j] = 0.0f;

            const float* h0p = &hs[(m0 + 0) * 132];
            const float* h1p = &hs[(m0 + 1) * 132];
            const float* h2p = &hs[(m0 + 2) * 132];
            const float* h3p = &hs[(m0 + 3) * 132];

            #pragma unroll 16
            for (int kk = 0; kk < 128; ++kk) {
                float4 w4 = *(const float4*)&Ws[kk * 64 + n0t];
                float hv0 = h0p[kk], hv1 = h1p[kk], hv2 = h2p[kk], hv3 = h3p[kk];
                acc[0][0] += hv0 * w4.x; acc[0][1] += hv0 * w4.y;
                acc[0][2] += hv0 * w4.z; acc[0][3] += hv0 * w4.w;
                acc[1][0] += hv1 * w4.x; acc[1][1] += hv1 * w4.y;
                acc[1][2] += hv1 * w4.z; acc[1][3] += hv1 * w4.w;
                acc[2][0] += hv2 * w4.x; acc[2][1] += hv2 * w4.y;
                acc[2][2] += hv2 * w4.z; acc[2][3] += hv2 * w4.w;
                acc[3][0] += hv3 * w4.x; acc[3][1] += hv3 * w4.y;
                acc[3][2] += hv3 * w4.z; acc[3][3] += hv3 * w4.w;
            }
            #pragma unroll
            for (int i = 0; i < 4; ++i)
                *(float4*)&pp[(m0 + i) * H_ + n0 + n0t] =
                    make_float4(acc[i][0], acc[i][1], acc[i][2], acc[i][3]);
        }
        grid_barrier();

        // reduce + tanh + in-place write; each CTA owns 512 elements
        {
            int base = blockIdx.x * 512;
            #pragma unroll
            for (int r = 0; r < 2; ++r) {
                int e = base + tid + r * 256;
                int m = e >> 10, n = e & (H_ - 1);
                int zidx = ((m << 9) + t) * H_ + n;       // (b*S_ + t)*H_ + n
                float s = Z[zidx];
                if (t > 0) {
                    #pragma unroll
                    for (int kq = 0; kq < 8; ++kq)
                        s += g_part[kq * (B_ * H_) + e];
                }
                float hv = tanhf(s);
                g_h[e] = hv;
                Z[zidx] = hv;
            }
        }
        grid_barrier();
    }

    // final hidden state -> d_out tail
    #pragma unroll
    for (int r = 0; r < 2; ++r) {
        int e = blockIdx.x * 512 + tid + r * 256;
        hid_out[e] = g_h[e];
    }
}

// ---------------- launch ----------------------------------------------------
extern "C" void kernel_launch(void* const* d_in, const int* in_sizes, int n_in,
                              void* d_out, int out_size)
{
    const int*   src    = (const int*)d_in[0];
    const float* emb    = (const float*)d_in[1];
    const float* W_ih0  = (const float*)d_in[2];
    const float* W_hh0  = (const float*)d_in[3];
    const float* b_ih0  = (const float*)d_in[4];
    const float* b_hh0  = (const float*)d_in[5];
    const float* W_ih1  = (const float*)d_in[6];
    const float* W_hh1  = (const float*)d_in[7];
    const float* b_ih1  = (const float*)d_in[8];
    const float* b_hh1  = (const float*)d_in[9];
    float* out = (float*)d_out;

    float* Z0p = nullptr;
    cudaGetSymbolAddress((void**)&Z0p, g_Z0);
    cudaFuncSetAttribute(rnn_recur_kernel,
                         cudaFuncAttributeMaxDynamicSharedMemorySize, RECUR_SMEM);

    // 1) src dtype probe
    detect_src_kernel<<<1, 256>>>(src);

    // 2) Z0 = emb[src] @ W_ih0 + b_ih0 + b_hh0   (gathered GEMM, K=512)
    gemm_bias_kernel<<<dim3(M0_ / 128, H_ / 64), 256>>>(
        nullptr, emb, src, W_ih0, b_ih0, b_hh0, Z0p, E_, 1);

    // 3) layer-0 recurrence (in-place: g_Z0 becomes H0), final h0 -> hidden[0]
    rnn_recur_kernel<<<GRID_R, 256, RECUR_SMEM>>>(W_hh0, Z0p, out + OUT_ELEMS);

    // 4) Z1 = H0 @ W_ih1 + b_ih1 + b_hh1  -> d_out outputs region (K=1024)
    gemm_bias_kernel<<<dim3(M0_ / 128, H_ / 64), 256>>>(
        Z0p, nullptr, nullptr, W_ih1, b_ih1, b_hh1, out, H_, 0);

    // 5) layer-1 recurrence in-place on d_out (Z1[t] -> h1_t = outputs),
    //    final h1 -> hidden[1]
    rnn_recur_kernel<<<GRID_R, 256, RECUR_SMEM>>>(
        W_hh1, out, out + OUT_ELEMS + B_ * H_);
}

// round 6
// speedup vs baseline: 1.1460x; 1.1460x over previous
#include <cuda_runtime.h>
#include <cuda_bf16.h>
#include <cstdint>

#define B_  64
#define S_  512
#define E_  512
#define H_  1024
#define M0_ 32768                 // B_*S_
#define OUT_ELEMS (M0_ * H_)      // 33554432
#define GRID_R 128
#define RECUR_SMEM ((128*64 + 64*132) * 4)   // Ws + hs = 66560 bytes

// ---------------- scratch (device globals; no allocation allowed) ----------
__device__ float          g_Z0[OUT_ELEMS];     // fp32 scratch: Z0, then h0
__device__ __nv_bfloat16  g_Whi0[1024 * 512];  // W_ih0 hi, [n][k]
__device__ __nv_bfloat16  g_Wlo0[1024 * 512];  // W_ih0 lo, [n][k]
__device__ __nv_bfloat16  g_Whi1[1024 * 1024]; // W_ih1 hi, [n][k]
__device__ __nv_bfloat16  g_Wlo1[1024 * 1024]; // W_ih1 lo, [n][k]
__device__ float          g_h[B_ * H_];        // current hidden state
__device__ float          g_part[8 * B_ * H_]; // k-split partial sums
__device__ unsigned       g_arrive;            // monotonic barrier counter
__device__ int            g_is64;              // src dtype flag

// ---------------- src dtype detection --------------------------------------
__global__ void detect_src_kernel(const int* __restrict__ src) {
    __shared__ int red[256];
    int acc = 0;
    for (int i = threadIdx.x; i < 4096; i += 256) acc |= src[2 * i + 1];
    red[threadIdx.x] = acc;
    __syncthreads();
    for (int s = 128; s > 0; s >>= 1) {
        if (threadIdx.x < s) red[threadIdx.x] |= red[threadIdx.x + s];
        __syncthreads();
    }
    if (threadIdx.x == 0) g_is64 = (red[0] == 0) ? 1 : 0;
}

// ---------------- software grid barrier ------------------------------------
__device__ __forceinline__ void grid_barrier() {
    __syncthreads();
    if (threadIdx.x == 0) {
        __threadfence();
        unsigned ticket = atomicAdd(&g_arrive, 1u);
        unsigned target = ticket - (ticket % (unsigned)GRID_R) + (unsigned)GRID_R;
        while ((int)(*(volatile unsigned*)&g_arrive - target) < 0) {
            __nanosleep(32);
        }
        __threadfence();
    }
    __syncthreads();
}

// ---------------- weight split + transpose: W[K,1024] -> Whi/Wlo [1024][K] --
__global__ void conv_w_kernel(const float* __restrict__ W,
                              __nv_bfloat16* __restrict__ Whi,
                              __nv_bfloat16* __restrict__ Wlo, int K) {
    __shared__ float tile[32][33];
    const int k0 = blockIdx.x * 32, n0 = blockIdx.y * 32;
    const int tx = threadIdx.x, ty = threadIdx.y;
    #pragma unroll
    for (int i = 0; i < 4; ++i)
        tile[ty + 8 * i][tx] = W[(size_t)(k0 + ty + 8 * i) * H_ + n0 + tx];
    __syncthreads();
    #pragma unroll
    for (int i = 0; i < 4; ++i) {
        int n = n0 + ty + 8 * i, k = k0 + tx;
        float w = tile[tx][ty + 8 * i];
        __nv_bfloat16 hi = __float2bfloat16(w);
        __nv_bfloat16 lo = __float2bfloat16(w - __bfloat162float(hi));
        Whi[(size_t)n * K + k] = hi;
        Wlo[(size_t)n * K + k] = lo;
    }
}

// ================== fused split-bf16 mma.sync GEMM ==========================
// C[M0,1024] = A @ W + b1 + b2 computed as Ahi*Whi + Ahi*Wlo + Alo*Whi.
// CTA tile 128x128, BK=32, 8 warps (warp tile 32x64). A loaded fp32 (register
// prefetch), split to hi/lo smem in-kernel. Smem pitch 40 bf16 (80 B, odd
// multiple of 16B -> conflict-free ldmatrix).
#define SPITCH 40
#define STILE  (128 * SPITCH)

__device__ __forceinline__ uint32_t smem_u32(const void* p) {
    uint32_t a;
    asm("{ .reg .u64 t; cvta.to.shared.u64 t, %1; cvt.u32.u64 %0, t; }"
        : "=r"(a) : "l"(p));
    return a;
}
__device__ __forceinline__ void ldsm4(uint32_t* r, uint32_t addr) {
    asm volatile("ldmatrix.sync.aligned.m8n8.x4.shared.b16 {%0,%1,%2,%3}, [%4];"
                 : "=r"(r[0]), "=r"(r[1]), "=r"(r[2]), "=r"(r[3]) : "r"(addr));
}
__device__ __forceinline__ void mma_bf16(float* d, const uint32_t* a,
                                         const uint32_t* b) {
    asm volatile(
        "mma.sync.aligned.m16n8k16.row.col.f32.bf16.bf16.f32 "
        "{%0,%1,%2,%3}, {%4,%5,%6,%7}, {%8,%9}, {%0,%1,%2,%3};"
        : "+f"(d[0]), "+f"(d[1]), "+f"(d[2]), "+f"(d[3])
        : "r"(a[0]), "r"(a[1]), "r"(a[2]), "r"(a[3]), "r"(b[0]), "r"(b[1]));
}
__device__ __forceinline__ uint2 split_hi4(float4 e) {
    __nv_bfloat162 p0, p1;
    p0.x = __float2bfloat16(e.x); p0.y = __float2bfloat16(e.y);
    p1.x = __float2bfloat16(e.z); p1.y = __float2bfloat16(e.w);
    uint2 r; r.x = *(uint32_t*)&p0; r.y = *(uint32_t*)&p1;
    return r;
}
__device__ __forceinline__ uint2 split_lo4(float4 e) {
    __nv_bfloat162 p0, p1;
    p0.x = __float2bfloat16(e.x - __bfloat162float(__float2bfloat16(e.x)));
    p0.y = __float2bfloat16(e.y - __bfloat162float(__float2bfloat16(e.y)));
    p1.x = __float2bfloat16(e.z - __bfloat162float(__float2bfloat16(e.z)));
    p1.y = __float2bfloat16(e.w - __bfloat162float(__float2bfloat16(e.w)));
    uint2 r; r.x = *(uint32_t*)&p0; r.y = *(uint32_t*)&p1;
    return r;
}

__global__ __launch_bounds__(256) void gemm_fused_kernel(
    const float* __restrict__ A,            // layer1 rows; null for gather
    const float* __restrict__ emb, const int* __restrict__ src,
    const __nv_bfloat16* __restrict__ Whi,  // [1024][K]
    const __nv_bfloat16* __restrict__ Wlo,  // [1024][K]
    const float* __restrict__ b1, const float* __restrict__ b2,
    float* __restrict__ C, int K, int gather)
{
    __shared__ __nv_bfloat16 sAhi[STILE], sAlo[STILE];
    __shared__ __nv_bfloat16 sWhi[STILE], sWlo[STILE];
    __shared__ int sidx[128];

    const int tid = threadIdx.x, wid = tid >> 5, lid = tid & 31;
    const int nb = blockIdx.x, mb = blockIdx.y;
    const int wm = wid & 3, wn = wid >> 2;

    if (gather && tid < 128) {
        int rg = mb * 128 + tid;
        sidx[tid] = g_is64 ? src[2 * rg] : src[rg];
    }
    __syncthreads();

    // ---- A-load task mapping: 1024 float4 tasks (128 rows x 8), 4/thread --
    const float* aptr[4];
    int arow[4], acol[4];
    #pragma unroll
    for (int i = 0; i < 4; ++i) {
        int task = tid + i * 256;
        arow[i] = task >> 3;
        acol[i] = (task & 7) * 4;
        aptr[i] = gather ? (emb + (size_t)sidx[arow[i]] * E_ + acol[i])
                         : (A + (size_t)(mb * 128 + arow[i]) * K + acol[i]);
    }
    // ---- W-load task mapping: 512 uint4 tasks per tile (128 rows x 4) -----
    int wrow[2], wcol[2];
    #pragma unroll
    for (int i = 0; i < 2; ++i) {
        int task = tid + i * 256;
        wrow[i] = task >> 2;
        wcol[i] = (task & 3) * 8;
    }
    const __nv_bfloat16* whibase = Whi + (size_t)(nb * 128) * K;
    const __nv_bfloat16* wlobase = Wlo + (size_t)(nb * 128) * K;

    const uint32_t sAhiU = smem_u32(sAhi), sAloU = smem_u32(sAlo);
    const uint32_t sWhiU = smem_u32(sWhi), sWloU = smem_u32(sWlo);

    // fragment smem addresses
    const int rA = (lid & 7) + ((lid >> 3) & 1) * 8;
    const int kA = ((lid >> 4) & 1) * 8;
    const int rB = (lid & 7) + ((lid >> 4) & 1) * 8;
    const int kB = ((lid >> 3) & 1) * 8;
    uint32_t aHiAddr[2], aLoAddr[2], bHiAddr[4], bLoAddr[4];
    #pragma unroll
    for (int mt = 0; mt < 2; ++mt) {
        uint32_t off = ((wm * 32 + mt * 16 + rA) * SPITCH + kA) * 2;
        aHiAddr[mt] = sAhiU + off; aLoAddr[mt] = sAloU + off;
    }
    #pragma unroll
    for (int bt = 0; bt < 4; ++bt) {
        uint32_t off = ((wn * 64 + bt * 16 + rB) * SPITCH + kB) * 2;
        bHiAddr[bt] = sWhiU + off; bLoAddr[bt] = sWloU + off;
    }

    float acc[2][8][4];
    #pragma unroll
    for (int mt = 0; mt < 2; ++mt)
        #pragma unroll
        for (int nt = 0; nt < 8; ++nt)
            #pragma unroll
            for (int j = 0; j < 4; ++j) acc[mt][nt][j] = 0.0f;

    const int nk = K >> 5;

    // prologue: stage chunk 0 in registers
    float4 astage[4];
    uint4  whstage[2], wlstage[2];
    #pragma unroll
    for (int i = 0; i < 4; ++i) astage[i] = *(const float4*)(aptr[i]);
    #pragma unroll
    for (int i = 0; i < 2; ++i) {
        whstage[i] = *(const uint4*)(whibase + (size_t)wrow[i] * K + wcol[i]);
        wlstage[i] = *(const uint4*)(wlobase + (size_t)wrow[i] * K + wcol[i]);
    }

    for (int kc = 0; kc < nk; ++kc) {
        __syncthreads();   // previous compute done reading smem
        // staged registers -> smem (convert A)
        #pragma unroll
        for (int i = 0; i < 4; ++i) {
            uint32_t off = (arow[i] * SPITCH + acol[i]) * 2;
            *(uint2*)((char*)sAhi + off) = split_hi4(astage[i]);
            *(uint2*)((char*)sAlo + off) = split_lo4(astage[i]);
        }
        #pragma unroll
        for (int i = 0; i < 2; ++i) {
            uint32_t off = (wrow[i] * SPITCH + wcol[i]) * 2;
            *(uint4*)((char*)sWhi + off) = whstage[i];
            *(uint4*)((char*)sWlo + off) = wlstage[i];
        }
        __syncthreads();

        // prefetch next chunk (overlaps with compute below)
        if (kc + 1 < nk) {
            const int kg = (kc + 1) * 32;
            #pragma unroll
            for (int i = 0; i < 4; ++i)
                astage[i] = *(const float4*)(aptr[i] + kg);
            #pragma unroll
            for (int i = 0; i < 2; ++i) {
                whstage[i] = *(const uint4*)(whibase + (size_t)wrow[i] * K + kg + wcol[i]);
                wlstage[i] = *(const uint4*)(wlobase + (size_t)wrow[i] * K + kg + wcol[i]);
            }
        }

        // compute: 3 products into the same accumulators
        #pragma unroll
        for (int kh = 0; kh < 2; ++kh) {
            uint32_t ah[2][4], al[2][4];
            #pragma unroll
            for (int mt = 0; mt < 2; ++mt) {
                ldsm4(ah[mt], aHiAddr[mt] + kh * 32);
                ldsm4(al[mt], aLoAddr[mt] + kh * 32);
            }
            #pragma unroll
            for (int bt = 0; bt < 4; ++bt) {
                uint32_t bh[4], bl[4];
                ldsm4(bh, bHiAddr[bt] + kh * 32);
                ldsm4(bl, bLoAddr[bt] + kh * 32);
                #pragma unroll
                for (int mt = 0; mt < 2; ++mt) {
                    mma_bf16(acc[mt][bt * 2 + 0], ah[mt], &bh[0]);
                    mma_bf16(acc[mt][bt * 2 + 1], ah[mt], &bh[2]);
                    mma_bf16(acc[mt][bt * 2 + 0], ah[mt], &bl[0]);
                    mma_bf16(acc[mt][bt * 2 + 1], ah[mt], &bl[2]);
                    mma_bf16(acc[mt][bt * 2 + 0], al[mt], &bh[0]);
                    mma_bf16(acc[mt][bt * 2 + 1], al[mt], &bh[2]);
                }
            }
        }
    }

    // epilogue: add biases, fp32 stores
    #pragma unroll
    for (int mt = 0; mt < 2; ++mt) {
        const int row0 = mb * 128 + wm * 32 + mt * 16 + (lid >> 2);
        #pragma unroll
        for (int nt = 0; nt < 8; ++nt) {
            const int col = nb * 128 + wn * 64 + nt * 8 + (lid & 3) * 2;
            const float bs0 = b1[col] + b2[col];
            const float bs1 = b1[col + 1] + b2[col + 1];
            float2 v0 = make_float2(acc[mt][nt][0] + bs0, acc[mt][nt][1] + bs1);
            float2 v1 = make_float2(acc[mt][nt][2] + bs0, acc[mt][nt][3] + bs1);
            *(float2*)&C[(size_t)row0 * H_ + col] = v0;
            *(float2*)&C[(size_t)(row0 + 8) * H_ + col] = v1;
        }
    }
}

// ---------------- persistent recurrence kernel (unchanged from R1) ----------
__global__ __launch_bounds__(256) void rnn_recur_kernel(
    const float* __restrict__ W, float* __restrict__ Z,
    float* __restrict__ hid_out)
{
    extern __shared__ float dyn[];
    float* Ws = dyn;             // [128][64]
    float* hs = dyn + 128 * 64;  // [64][132]

    const int tid = threadIdx.x;
    const int nb = blockIdx.x & 15, ks = blockIdx.x >> 4;
    const int n0 = nb * 64, k0 = ks * 128;

    for (int i = tid; i < 2048; i += 256) {
        int kk = i >> 4, q = i & 15;
        *(float4*)&Ws[kk * 64 + (q << 2)] =
            *(const float4*)&W[(size_t)(k0 + kk) * H_ + n0 + (q << 2)];
    }
    __syncthreads();

    const int mt = tid >> 4, nt = tid & 15;
    const int m0 = mt * 4, n0t = nt * 4;
    float* pp = &g_part[ks * (B_ * H_)];

    for (int t = 0; t < S_; ++t) {
        if (t > 0) {
            for (int i = tid; i < 2048; i += 256) {
                int m = i >> 5, q = i & 31;
                *(float4*)&hs[m * 132 + (q << 2)] =
                    *(const float4*)&g_h[m * H_ + k0 + (q << 2)];
            }
            __syncthreads();

            float acc[4][4];
            #pragma unroll
            for (int i = 0; i < 4; ++i)
                #pragma unroll
                for (int j = 0; j < 4; ++j) acc[i][j] = 0.0f;

            const float* h0p = &hs[(m0 + 0) * 132];
            const float* h1p = &hs[(m0 + 1) * 132];
            const float* h2p = &hs[(m0 + 2) * 132];
            const float* h3p = &hs[(m0 + 3) * 132];

            #pragma unroll 16
            for (int kk = 0; kk < 128; ++kk) {
                float4 w4 = *(const float4*)&Ws[kk * 64 + n0t];
                float hv0 = h0p[kk], hv1 = h1p[kk], hv2 = h2p[kk], hv3 = h3p[kk];
                acc[0][0] += hv0 * w4.x; acc[0][1] += hv0 * w4.y;
                acc[0][2] += hv0 * w4.z; acc[0][3] += hv0 * w4.w;
                acc[1][0] += hv1 * w4.x; acc[1][1] += hv1 * w4.y;
                acc[1][2] += hv1 * w4.z; acc[1][3] += hv1 * w4.w;
                acc[2][0] += hv2 * w4.x; acc[2][1] += hv2 * w4.y;
                acc[2][2] += hv2 * w4.z; acc[2][3] += hv2 * w4.w;
                acc[3][0] += hv3 * w4.x; acc[3][1] += hv3 * w4.y;
                acc[3][2] += hv3 * w4.z; acc[3][3] += hv3 * w4.w;
            }
            #pragma unroll
            for (int i = 0; i < 4; ++i)
                *(float4*)&pp[(m0 + i) * H_ + n0 + n0t] =
                    make_float4(acc[i][0], acc[i][1], acc[i][2], acc[i][3]);
        }
        grid_barrier();

        {
            int base = blockIdx.x * 512;
            #pragma unroll
            for (int r = 0; r < 2; ++r) {
                int e = base + tid + r * 256;
                int m = e >> 10, n = e & (H_ - 1);
                int zidx = ((m << 9) + t) * H_ + n;
                float s = Z[zidx];
                if (t > 0) {
                    #pragma unroll
                    for (int kq = 0; kq < 8; ++kq)
                        s += g_part[kq * (B_ * H_) + e];
                }
                float hv = tanhf(s);
                g_h[e] = hv;
                Z[zidx] = hv;
            }
        }
        grid_barrier();
    }

    #pragma unroll
    for (int r = 0; r < 2; ++r) {
        int e = blockIdx.x * 512 + tid + r * 256;
        hid_out[e] = g_h[e];
    }
}

// ---------------- launch ----------------------------------------------------
extern "C" void kernel_launch(void* const* d_in, const int* in_sizes, int n_in,
                              void* d_out, int out_size)
{
    const int*   src    = (const int*)d_in[0];
    const float* emb    = (const float*)d_in[1];
    const float* W_ih0  = (const float*)d_in[2];
    const float* W_hh0  = (const float*)d_in[3];
    const float* b_ih0  = (const float*)d_in[4];
    const float* b_hh0  = (const float*)d_in[5];
    const float* W_ih1  = (const float*)d_in[6];
    const float* W_hh1  = (const float*)d_in[7];
    const float* b_ih1  = (const float*)d_in[8];
    const float* b_hh1  = (const float*)d_in[9];
    float* out = (float*)d_out;

    float* Z0p = nullptr;
    __nv_bfloat16 *Whi0 = nullptr, *Wlo0 = nullptr, *Whi1 = nullptr, *Wlo1 = nullptr;
    cudaGetSymbolAddress((void**)&Z0p, g_Z0);
    cudaGetSymbolAddress((void**)&Whi0, g_Whi0);
    cudaGetSymbolAddress((void**)&Wlo0, g_Wlo0);
    cudaGetSymbolAddress((void**)&Whi1, g_Whi1);
    cudaGetSymbolAddress((void**)&Wlo1, g_Wlo1);
    cudaFuncSetAttribute(rnn_recur_kernel,
                         cudaFuncAttributeMaxDynamicSharedMemorySize, RECUR_SMEM);

    // 1) src dtype probe + weight split/transpose (small)
    detect_src_kernel<<<1, 256>>>(src);
    conv_w_kernel<<<dim3(512 / 32, 32), dim3(32, 8)>>>(W_ih0, Whi0, Wlo0, 512);
    conv_w_kernel<<<dim3(1024 / 32, 32), dim3(32, 8)>>>(W_ih1, Whi1, Wlo1, 1024);

    // 2) Z0 = emb[src] @ W_ih0 + b  (fused split-bf16 mma.sync, K=512)
    gemm_fused_kernel<<<dim3(8, 256), 256>>>(
        nullptr, emb, src, Whi0, Wlo0, b_ih0, b_hh0, Z0p, 512, 1);

    // 3) layer-0 recurrence (in-place on g_Z0), final h0 -> hidden[0]
    rnn_recur_kernel<<<GRID_R, 256, RECUR_SMEM>>>(W_hh0, Z0p, out + OUT_ELEMS);

    // 4) Z1 = H0 @ W_ih1 + b -> d_out  (fused split-bf16 mma.sync, K=1024)
    gemm_fused_kernel<<<dim3(8, 256), 256>>>(
        Z0p, nullptr, nullptr, Whi1, Wlo1, b_ih1, b_hh1, out, 1024, 0);

    // 5) layer-1 recurrence in-place on d_out, final h1 -> hidden[1]
    rnn_recur_kernel<<<GRID_R, 256, RECUR_SMEM>>>(
        W_hh1, out, out + OUT_ELEMS + B_ * H_);
}

// round 9
// speedup vs baseline: 1.5057x; 1.3139x over previous
#include <cuda_runtime.h>
#include <cuda_bf16.h>
#include <cstdint>

#define B_  64
#define S_  512
#define E_  512
#define H_  1024
#define M0_ 32768                 // B_*S_
#define OUT_ELEMS (M0_ * H_)      // 33554432
#define GRID_R 128

// recurrence smem: sWhi/sWlo [32][264] + sAhi/sAlo [64][264], bf16
#define RSM_PITCH 264
#define RSMEM ((32 * RSM_PITCH + 64 * RSM_PITCH) * 2 * 2)   // 101376 bytes

// ---------------- scratch (device globals; no allocation allowed) ----------
__device__ float          g_Z0[OUT_ELEMS];      // fp32 scratch: Z0, then H0
__device__ __nv_bfloat16  g_Whi0[1024 * 512];   // W_ih0 hi, [n][k]
__device__ __nv_bfloat16  g_Wlo0[1024 * 512];   // W_ih0 lo
__device__ __nv_bfloat16  g_Whi1[1024 * 1024];  // W_ih1 hi
__device__ __nv_bfloat16  g_Wlo1[1024 * 1024];  // W_ih1 lo
__device__ __nv_bfloat16  g_Rhi0[1024 * 1024];  // W_hh0 hi, [n][k]
__device__ __nv_bfloat16  g_Rlo0[1024 * 1024];  // W_hh0 lo
__device__ __nv_bfloat16  g_Rhi1[1024 * 1024];  // W_hh1 hi
__device__ __nv_bfloat16  g_Rlo1[1024 * 1024];  // W_hh1 lo
__device__ __nv_bfloat16  g_hhi[B_ * H_];       // hidden hi (bf16)
__device__ __nv_bfloat16  g_hlo[B_ * H_];       // hidden lo (bf16)
__device__ float          g_part[4 * B_ * H_];  // k-split partial sums
__device__ unsigned       g_arrive;             // global ticket barrier
__device__ int            g_is64;               // src dtype flag

// ---------------- src dtype detection --------------------------------------
__global__ void detect_src_kernel(const int* __restrict__ src) {
    __shared__ int red[256];
    int acc = 0;
    for (int i = threadIdx.x; i < 4096; i += 256) acc |= src[2 * i + 1];
    red[threadIdx.x] = acc;
    __syncthreads();
    for (int s = 128; s > 0; s >>= 1) {
        if (threadIdx.x < s) red[threadIdx.x] |= red[threadIdx.x + s];
        __syncthreads();
    }
    if (threadIdx.x == 0) g_is64 = (red[0] == 0) ? 1 : 0;
}

// ---------------- software grid barrier (monotonic tickets, R1-proven) ------
__device__ __forceinline__ void grid_barrier() {
    __syncthreads();
    if (threadIdx.x == 0) {
        __threadfence();
        unsigned ticket = atomicAdd(&g_arrive, 1u);
        unsigned target = ticket - (ticket % (unsigned)GRID_R) + (unsigned)GRID_R;
        while ((int)(*(volatile unsigned*)&g_arrive - target) < 0) {
            __nanosleep(32);
        }
        __threadfence();
    }
    __syncthreads();
}

// ---------------- weight split + transpose: W[K,1024] -> hi/lo [1024][K] ----
__global__ void conv_w_kernel(const float* __restrict__ W,
                              __nv_bfloat16* __restrict__ Whi,
                              __nv_bfloat16* __restrict__ Wlo, int K) {
    __shared__ float tile[32][33];
    const int k0 = blockIdx.x * 32, n0 = blockIdx.y * 32;
    const int tx = threadIdx.x, ty = threadIdx.y;
    #pragma unroll
    for (int i = 0; i < 4; ++i)
        tile[ty + 8 * i][tx] = W[(size_t)(k0 + ty + 8 * i) * H_ + n0 + tx];
    __syncthreads();
    #pragma unroll
    for (int i = 0; i < 4; ++i) {
        int n = n0 + ty + 8 * i, k = k0 + tx;
        float w = tile[tx][ty + 8 * i];
        __nv_bfloat16 hi = __float2bfloat16(w);
        __nv_bfloat16 lo = __float2bfloat16(w - __bfloat162float(hi));
        Whi[(size_t)n * K + k] = hi;
        Wlo[(size_t)n * K + k] = lo;
    }
}

// ================== shared mma.sync helpers =================================
__device__ __forceinline__ uint32_t smem_u32(const void* p) {
    uint32_t a;
    asm("{ .reg .u64 t; cvta.to.shared.u64 t, %1; cvt.u32.u64 %0, t; }"
        : "=r"(a) : "l"(p));
    return a;
}
__device__ __forceinline__ void ldsm4(uint32_t* r, uint32_t addr) {
    asm volatile("ldmatrix.sync.aligned.m8n8.x4.shared.b16 {%0,%1,%2,%3}, [%4];"
                 : "=r"(r[0]), "=r"(r[1]), "=r"(r[2]), "=r"(r[3]) : "r"(addr));
}
__device__ __forceinline__ void mma_bf16(float* d, const uint32_t* a,
                                         const uint32_t* b) {
    asm volatile(
        "mma.sync.aligned.m16n8k16.row.col.f32.bf16.bf16.f32 "
        "{%0,%1,%2,%3}, {%4,%5,%6,%7}, {%8,%9}, {%0,%1,%2,%3};"
        : "+f"(d[0]), "+f"(d[1]), "+f"(d[2]), "+f"(d[3])
        : "r"(a[0]), "r"(a[1]), "r"(a[2]), "r"(a[3]), "r"(b[0]), "r"(b[1]));
}
__device__ __forceinline__ uint2 split_hi4(float4 e) {
    __nv_bfloat162 p0, p1;
    p0.x = __float2bfloat16(e.x); p0.y = __float2bfloat16(e.y);
    p1.x = __float2bfloat16(e.z); p1.y = __float2bfloat16(e.w);
    uint2 r; r.x = *(uint32_t*)&p0; r.y = *(uint32_t*)&p1;
    return r;
}
__device__ __forceinline__ uint2 split_lo4(float4 e) {
    __nv_bfloat162 p0, p1;
    p0.x = __float2bfloat16(e.x - __bfloat162float(__float2bfloat16(e.x)));
    p0.y = __float2bfloat16(e.y - __bfloat162float(__float2bfloat16(e.y)));
    p1.x = __float2bfloat16(e.z - __bfloat162float(__float2bfloat16(e.z)));
    p1.y = __float2bfloat16(e.w - __bfloat162float(__float2bfloat16(e.w)));
    uint2 r; r.x = *(uint32_t*)&p0; r.y = *(uint32_t*)&p1;
    return r;
}

// ================== fused split-bf16 mma.sync GEMM (R6, unchanged) ==========
#define SPITCH 40
#define STILE  (128 * SPITCH)

__global__ __launch_bounds__(256) void gemm_fused_kernel(
    const float* __restrict__ A,
    const float* __restrict__ emb, const int* __restrict__ src,
    const __nv_bfloat16* __restrict__ Whi,
    const __nv_bfloat16* __restrict__ Wlo,
    const float* __restrict__ b1, const float* __restrict__ b2,
    float* __restrict__ C, int K, int gather)
{
    __shared__ __nv_bfloat16 sAhi[STILE], sAlo[STILE];
    __shared__ __nv_bfloat16 sWhi[STILE], sWlo[STILE];
    __shared__ int sidx[128];

    const int tid = threadIdx.x, wid = tid >> 5, lid = tid & 31;
    const int nb = blockIdx.x, mb = blockIdx.y;
    const int wm = wid & 3, wn = wid >> 2;

    if (gather && tid < 128) {
        int rg = mb * 128 + tid;
        sidx[tid] = g_is64 ? src[2 * rg] : src[rg];
    }
    __syncthreads();

    const float* aptr[4];
    int arow[4], acol[4];
    #pragma unroll
    for (int i = 0; i < 4; ++i) {
        int task = tid + i * 256;
        arow[i] = task >> 3;
        acol[i] = (task & 7) * 4;
        aptr[i] = gather ? (emb + (size_t)sidx[arow[i]] * E_ + acol[i])
                         : (A + (size_t)(mb * 128 + arow[i]) * K + acol[i]);
    }
    int wrow[2], wcol[2];
    #pragma unroll
    for (int i = 0; i < 2; ++i) {
        int task = tid + i * 256;
        wrow[i] = task >> 2;
        wcol[i] = (task & 3) * 8;
    }
    const __nv_bfloat16* whibase = Whi + (size_t)(nb * 128) * K;
    const __nv_bfloat16* wlobase = Wlo + (size_t)(nb * 128) * K;

    const uint32_t sAhiU = smem_u32(sAhi), sAloU = smem_u32(sAlo);
    const uint32_t sWhiU = smem_u32(sWhi), sWloU = smem_u32(sWlo);

    const int rA = (lid & 7) + ((lid >> 3) & 1) * 8;
    const int kA = ((lid >> 4) & 1) * 8;
    const int rB = (lid & 7) + ((lid >> 4) & 1) * 8;
    const int kB = ((lid >> 3) & 1) * 8;
    uint32_t aHiAddr[2], aLoAddr[2], bHiAddr[4], bLoAddr[4];
    #pragma unroll
    for (int mt = 0; mt < 2; ++mt) {
        uint32_t off = ((wm * 32 + mt * 16 + rA) * SPITCH + kA) * 2;
        aHiAddr[mt] = sAhiU + off; aLoAddr[mt] = sAloU + off;
    }
    #pragma unroll
    for (int bt = 0; bt < 4; ++bt) {
        uint32_t off = ((wn * 64 + bt * 16 + rB) * SPITCH + kB) * 2;
        bHiAddr[bt] = sWhiU + off; bLoAddr[bt] = sWloU + off;
    }

    float acc[2][8][4];
    #pragma unroll
    for (int mt = 0; mt < 2; ++mt)
        #pragma unroll
        for (int nt = 0; nt < 8; ++nt)
            #pragma unroll
            for (int j = 0; j < 4; ++j) acc[mt][nt][j] = 0.0f;

    const int nk = K >> 5;

    float4 astage[4];
    uint4  whstage[2], wlstage[2];
    #pragma unroll
    for (int i = 0; i < 4; ++i) astage[i] = *(const float4*)(aptr[i]);
    #pragma unroll
    for (int i = 0; i < 2; ++i) {
        whstage[i] = *(const uint4*)(whibase + (size_t)wrow[i] * K + wcol[i]);
        wlstage[i] = *(const uint4*)(wlobase + (size_t)wrow[i] * K + wcol[i]);
    }

    for (int kc = 0; kc < nk; ++kc) {
        __syncthreads();
        #pragma unroll
        for (int i = 0; i < 4; ++i) {
            uint32_t off = (arow[i] * SPITCH + acol[i]) * 2;
            *(uint2*)((char*)sAhi + off) = split_hi4(astage[i]);
            *(uint2*)((char*)sAlo + off) = split_lo4(astage[i]);
        }
        #pragma unroll
        for (int i = 0; i < 2; ++i) {
            uint32_t off = (wrow[i] * SPITCH + wcol[i]) * 2;
            *(uint4*)((char*)sWhi + off) = whstage[i];
            *(uint4*)((char*)sWlo + off) = wlstage[i];
        }
        __syncthreads();

        if (kc + 1 < nk) {
            const int kg = (kc + 1) * 32;
            #pragma unroll
            for (int i = 0; i < 4; ++i)
                astage[i] = *(const float4*)(aptr[i] + kg);
            #pragma unroll
            for (int i = 0; i < 2; ++i) {
                whstage[i] = *(const uint4*)(whibase + (size_t)wrow[i] * K + kg + wcol[i]);
                wlstage[i] = *(const uint4*)(wlobase + (size_t)wrow[i] * K + kg + wcol[i]);
            }
        }

        #pragma unroll
        for (int kh = 0; kh < 2; ++kh) {
            uint32_t ah[2][4], al[2][4];
            #pragma unroll
            for (int mt = 0; mt < 2; ++mt) {
                ldsm4(ah[mt], aHiAddr[mt] + kh * 32);
                ldsm4(al[mt], aLoAddr[mt] + kh * 32);
            }
            #pragma unroll
            for (int bt = 0; bt < 4; ++bt) {
                uint32_t bh[4], bl[4];
                ldsm4(bh, bHiAddr[bt] + kh * 32);
                ldsm4(bl, bLoAddr[bt] + kh * 32);
                #pragma unroll
                for (int mt = 0; mt < 2; ++mt) {
                    mma_bf16(acc[mt][bt * 2 + 0], ah[mt], &bh[0]);
                    mma_bf16(acc[mt][bt * 2 + 1], ah[mt], &bh[2]);
                    mma_bf16(acc[mt][bt * 2 + 0], ah[mt], &bl[0]);
                    mma_bf16(acc[mt][bt * 2 + 1], ah[mt], &bl[2]);
                    mma_bf16(acc[mt][bt * 2 + 0], al[mt], &bh[0]);
                    mma_bf16(acc[mt][bt * 2 + 1], al[mt], &bh[2]);
                }
            }
        }
    }

    #pragma unroll
    for (int mt = 0; mt < 2; ++mt) {
        const int row0 = mb * 128 + wm * 32 + mt * 16 + (lid >> 2);
        #pragma unroll
        for (int nt = 0; nt < 8; ++nt) {
            const int col = nb * 128 + wn * 64 + nt * 8 + (lid & 3) * 2;
            const float bs0 = b1[col] + b2[col];
            const float bs1 = b1[col + 1] + b2[col + 1];
            float2 v0 = make_float2(acc[mt][nt][0] + bs0, acc[mt][nt][1] + bs1);
            float2 v1 = make_float2(acc[mt][nt][2] + bs0, acc[mt][nt][3] + bs1);
            *(float2*)&C[(size_t)row0 * H_ + col] = v0;
            *(float2*)&C[(size_t)(row0 + 8) * H_ + col] = v1;
        }
    }
}

// ================== tensor-core persistent recurrence =======================
// h_t = tanh(Z[t] + h_{t-1} @ W_hh), W in split bf16 [n][k].
// 128 CTAs = 32 N-blocks (32 cols) x 4 K-splits (256 rows). 8 warps:
// warp tile m16 x n16, K=256 full. h stored globally as bf16 hi/lo.
// Sync skeleton identical to R1's proven kernel: two full grid barriers/step.
__global__ __launch_bounds__(256) void rnn_recur_tc(
    const __nv_bfloat16* __restrict__ Rhi, const __nv_bfloat16* __restrict__ Rlo,
    float* __restrict__ Z, float* __restrict__ hid_out)
{
    extern __shared__ __nv_bfloat16 sm[];
    __nv_bfloat16* sWhi = sm;                        // [32][264]
    __nv_bfloat16* sWlo = sm + 32 * RSM_PITCH;
    __nv_bfloat16* sAhi = sm + 64 * RSM_PITCH;       // [64][264]
    __nv_bfloat16* sAlo = sm + 128 * RSM_PITCH;

    const int tid = threadIdx.x, wid = tid >> 5, lid = tid & 31;
    const int nb = blockIdx.x & 31, ks = blockIdx.x >> 5;
    const int n0 = nb * 32, k0 = ks * 256;

    // persistent W slice load: 32 rows x 32 uint4 per array
    #pragma unroll
    for (int i = 0; i < 4; ++i) {
        int task = tid + i * 256;
        int r = task >> 5, c = task & 31;
        *(uint4*)(sWhi + r * RSM_PITCH + c * 8) =
            *((const uint4*)(Rhi + (size_t)(n0 + r) * 1024 + k0) + c);
        *(uint4*)(sWlo + r * RSM_PITCH + c * 8) =
            *((const uint4*)(Rlo + (size_t)(n0 + r) * 1024 + k0) + c);
    }
    __syncthreads();

    const int wm = wid & 3, wn = wid >> 2;           // 4 m-tiles x 2 n-tiles
    const int rA = (lid & 7) + ((lid >> 3) & 1) * 8;
    const int kA = ((lid >> 4) & 1) * 8;
    const int rB = (lid & 7) + ((lid >> 4) & 1) * 8;
    const int kB = ((lid >> 3) & 1) * 8;
    const uint32_t aHi = smem_u32(sAhi) + ((wm * 16 + rA) * RSM_PITCH + kA) * 2;
    const uint32_t aLo = smem_u32(sAlo) + ((wm * 16 + rA) * RSM_PITCH + kA) * 2;
    const uint32_t bHi = smem_u32(sWhi) + ((wn * 16 + rB) * RSM_PITCH + kB) * 2;
    const uint32_t bLo = smem_u32(sWlo) + ((wn * 16 + rB) * RSM_PITCH + kB) * 2;

    for (int t = 0; t < S_; ++t) {
        if (t > 0) {
            // stage h slice [64][256] hi/lo
            #pragma unroll
            for (int i = 0; i < 8; ++i) {
                int task = tid + i * 256;
                int r = task >> 5, c = task & 31;
                *(uint4*)(sAhi + r * RSM_PITCH + c * 8) =
                    *((const uint4*)(g_hhi + (size_t)r * 1024 + k0) + c);
                *(uint4*)(sAlo + r * RSM_PITCH + c * 8) =
                    *((const uint4*)(g_hlo + (size_t)r * 1024 + k0) + c);
            }
            __syncthreads();

            float accM[2][4] = {{0, 0, 0, 0}, {0, 0, 0, 0}};
            float accC[2][4] = {{0, 0, 0, 0}, {0, 0, 0, 0}};
            #pragma unroll 4
            for (int k = 0; k < 16; ++k) {
                uint32_t ah[4], al[4], bh[4], bl[4];
                ldsm4(ah, aHi + k * 32);
                ldsm4(al, aLo + k * 32);
                ldsm4(bh, bHi + k * 32);
                ldsm4(bl, bLo + k * 32);
                mma_bf16(accM[0], ah, &bh[0]);
                mma_bf16(accM[1], ah, &bh[2]);
                mma_bf16(accC[0], ah, &bl[0]);
                mma_bf16(accC[1], ah, &bl[2]);
                mma_bf16(accC[0], al, &bh[0]);
                mma_bf16(accC[1], al, &bh[2]);
            }
            // partials -> global
            #pragma unroll
            for (int nt = 0; nt < 2; ++nt) {
                int m = wm * 16 + (lid >> 2);
                int n = n0 + wn * 16 + nt * 8 + (lid & 3) * 2;
                *(float2*)&g_part[ks * (B_ * H_) + m * 1024 + n] =
                    make_float2(accM[nt][0] + accC[nt][0], accM[nt][1] + accC[nt][1]);
                *(float2*)&g_part[ks * (B_ * H_) + (m + 8) * 1024 + n] =
                    make_float2(accM[nt][2] + accC[nt][2], accM[nt][3] + accC[nt][3]);
            }
        }
        grid_barrier();

        // phase B: this CTA owns m in [16ks,16ks+16), n in [n0,n0+32)
        {
            int ml = tid >> 4, nl = (tid & 15) * 2;
            int m = ks * 16 + ml, n = n0 + nl;
            int zidx = ((m << 9) + t) * H_ + n;
            float2 s = *(float2*)&Z[zidx];
            if (t > 0) {
                #pragma unroll
                for (int q = 0; q < 4; ++q) {
                    float2 p = *(float2*)&g_part[q * (B_ * H_) + m * 1024 + n];
                    s.x += p.x; s.y += p.y;
                }
            }
            float h0 = tanhf(s.x), h1 = tanhf(s.y);
            *(float2*)&Z[zidx] = make_float2(h0, h1);
            __nv_bfloat162 hi, lo;
            hi.x = __float2bfloat16(h0);
            hi.y = __float2bfloat16(h1);
            lo.x = __float2bfloat16(h0 - __bfloat162float(hi.x));
            lo.y = __float2bfloat16(h1 - __bfloat162float(hi.y));
            *(uint32_t*)(g_hhi + m * 1024 + n) = *(uint32_t*)&hi;
            *(uint32_t*)(g_hlo + m * 1024 + n) = *(uint32_t*)&lo;
            if (t == S_ - 1)
                *(float2*)&hid_out[m * 1024 + n] = make_float2(h0, h1);
        }
        grid_barrier();
    }
}

// ---------------- launch ----------------------------------------------------
extern "C" void kernel_launch(void* const* d_in, const int* in_sizes, int n_in,
                              void* d_out, int out_size)
{
    const int*   src    = (const int*)d_in[0];
    const float* emb    = (const float*)d_in[1];
    const float* W_ih0  = (const float*)d_in[2];
    const float* W_hh0  = (const float*)d_in[3];
    const float* b_ih0  = (const float*)d_in[4];
    const float* b_hh0  = (const float*)d_in[5];
    const float* W_ih1  = (const float*)d_in[6];
    const float* W_hh1  = (const float*)d_in[7];
    const float* b_ih1  = (const float*)d_in[8];
    const float* b_hh1  = (const float*)d_in[9];
    float* out = (float*)d_out;

    float* Z0p = nullptr;
    __nv_bfloat16 *Whi0, *Wlo0, *Whi1, *Wlo1, *Rhi0, *Rlo0, *Rhi1, *Rlo1;
    cudaGetSymbolAddress((void**)&Z0p, g_Z0);
    cudaGetSymbolAddress((void**)&Whi0, g_Whi0);
    cudaGetSymbolAddress((void**)&Wlo0, g_Wlo0);
    cudaGetSymbolAddress((void**)&Whi1, g_Whi1);
    cudaGetSymbolAddress((void**)&Wlo1, g_Wlo1);
    cudaGetSymbolAddress((void**)&Rhi0, g_Rhi0);
    cudaGetSymbolAddress((void**)&Rlo0, g_Rlo0);
    cudaGetSymbolAddress((void**)&Rhi1, g_Rhi1);
    cudaGetSymbolAddress((void**)&Rlo1, g_Rlo1);
    cudaFuncSetAttribute(rnn_recur_tc,
                         cudaFuncAttributeMaxDynamicSharedMemorySize, RSMEM);

    // 1) src dtype probe + weight split/transpose
    detect_src_kernel<<<1, 256>>>(src);
    conv_w_kernel<<<dim3(512 / 32, 32), dim3(32, 8)>>>(W_ih0, Whi0, Wlo0, 512);
    conv_w_kernel<<<dim3(1024 / 32, 32), dim3(32, 8)>>>(W_ih1, Whi1, Wlo1, 1024);
    conv_w_kernel<<<dim3(1024 / 32, 32), dim3(32, 8)>>>(W_hh0, Rhi0, Rlo0, 1024);
    conv_w_kernel<<<dim3(1024 / 32, 32), dim3(32, 8)>>>(W_hh1, Rhi1, Rlo1, 1024);

    // 2) Z0 = emb[src] @ W_ih0 + b  (fused split-bf16 mma.sync, K=512)
    gemm_fused_kernel<<<dim3(8, 256), 256>>>(
        nullptr, emb, src, Whi0, Wlo0, b_ih0, b_hh0, Z0p, 512, 1);

    // 3) layer-0 tensor-core recurrence (in-place on g_Z0), h0 -> hidden[0]
    rnn_recur_tc<<<GRID_R, 256, RSMEM>>>(Rhi0, Rlo0, Z0p, out + OUT_ELEMS);

    // 4) Z1 = H0 @ W_ih1 + b -> d_out  (fused split-bf16 mma.sync, K=1024)
    gemm_fused_kernel<<<dim3(8, 256), 256>>>(
        Z0p, nullptr, nullptr, Whi1, Wlo1, b_ih1, b_hh1, out, 1024, 0);

    // 5) layer-1 tensor-core recurrence in-place on d_out, h1 -> hidden[1]
    rnn_recur_tc<<<GRID_R, 256, RSMEM>>>(
        Rhi1, Rlo1, out, out + OUT_ELEMS + B_ * H_);
}